// round 16
// baseline (speedup 1.0000x reference)
#include <cuda_runtime.h>
#include <cuda_bf16.h>
#include <cstdint>
#include <cstddef>

#define NN 100000
#define DD 128
#define AA 3
#define PP 50000
#define EE 500000
#define EFN 500000

#define ND  ((size_t)NN * DD)
#define PD  ((size_t)PP * DD)
#define NBLK 98   // (NN + 1023) / 1024
#define ROWW 128  // split row: 64 hi words + 64 lo words

// ---------------- scratch (static device globals; no allocation) ----------------
__device__ float    g_hbuf[AA * PP * DD];                  // h rows, f32 (mixed with xa in step6)
__device__ __align__(16) uint32_t g_xbs [AA * NN * ROWW];  // x_att_b, split
__device__ __align__(16) uint32_t g_aggs[4 * NN * ROWW];   // agg slots 0-2 + family slot 3, split
// pre-split weights: slot = 16384 words, layout [n*128 + w] hi, [n*128 + 64 + w] lo
// slots: 0 aggW1, 1-3 wl1, 4-6 wr1, 7-9 wl2, 10-12 wr2, 13 wl3, 14 wr3,
//        15-17 proj, 18-20 MT (inv), 21-23 C (fold)
__device__ __align__(16) uint32_t g_ws[24 * 16384];
// CSR: g_fillip = [7*NN fill cursors][NN ipop]
__device__ int    g_fillip[8 * NN];
__device__ int    g_rowptr[7 * (NN + 1)];
__device__ int    g_eord  [7 * EE];
__device__ int    g_bsum  [7 * NBLK];

// m16n8k16 bf16 mma (sm_80+ portable)
__device__ __forceinline__ void mma16(float* c, const uint32_t* a, uint32_t b0, uint32_t b1) {
    asm volatile("mma.sync.aligned.m16n8k16.row.col.f32.bf16.bf16.f32 "
                 "{%0,%1,%2,%3}, {%4,%5,%6,%7}, {%8,%9}, {%0,%1,%2,%3};"
                 : "+f"(c[0]), "+f"(c[1]), "+f"(c[2]), "+f"(c[3])
                 : "r"(a[0]), "r"(a[1]), "r"(a[2]), "r"(a[3]), "r"(b0), "r"(b1));
}
// split (x,y) into packed bf16x2 hi + lo
__device__ __forceinline__ uint32_t packsplit(float x, float y, uint32_t& lopack) {
    float hx = __bfloat162float(__float2bfloat16(x));
    float hy = __bfloat162float(__float2bfloat16(y));
    uint32_t hi;
    asm("cvt.rn.bf16x2.f32 %0, %1, %2;" : "=r"(hi) : "f"(hy), "f"(hx));
    asm("cvt.rn.bf16x2.f32 %0, %1, %2;" : "=r"(lopack) : "f"(y - hy), "f"(x - hx));
    return hi;
}
__device__ __forceinline__ float2 bf2f(uint32_t u) {
    __nv_bfloat162 b = *reinterpret_cast<__nv_bfloat162*>(&u);
    return __bfloat1622float2(b);
}

// ---------------- weight pre-split: f32 [n][k] -> split slot ---------------------
__global__ __launch_bounds__(1024)
void wconv(const float* __restrict__ aggW, const float* __restrict__ wl1,
           const float* __restrict__ wr1, const float* __restrict__ wl2,
           const float* __restrict__ wr2, const float* __restrict__ wl3,
           const float* __restrict__ wr3, const float* __restrict__ proj) {
    int b = blockIdx.x;
    const float* src; int st;
    if (b == 0)       { src = aggW;                   st = 256; }
    else if (b < 4)   { src = wl1 + (b - 1) * 16384;  st = 128; }
    else if (b < 7)   { src = wr1 + (b - 4) * 16384;  st = 128; }
    else if (b < 10)  { src = wl2 + (b - 7) * 16384;  st = 128; }
    else if (b < 13)  { src = wr2 + (b - 10) * 16384; st = 128; }
    else if (b == 13) { src = wl3;                    st = 128; }
    else if (b == 14) { src = wr3;                    st = 128; }
    else              { src = proj + (b - 15) * 16384; st = 128; }
    uint32_t* dh = g_ws + (size_t)b * 16384;
    for (int idx = threadIdx.x; idx < 8192; idx += 1024) {
        int n = idx >> 6, w = idx & 63;
        float x = src[(size_t)n * st + 2 * w];
        float y = src[(size_t)n * st + 2 * w + 1];
        uint32_t lo;
        uint32_t hi = packsplit(x, y, lo);
        dh[n * 128 + w]      = hi;
        dh[n * 128 + 64 + w] = lo;
    }
}

// ---------------- ipop: node -> population position + 1 --------------------------
__global__ void ipop_k(const int* __restrict__ pop) {
    int i = blockIdx.x * blockDim.x + threadIdx.x;
    if (i < PP) g_fillip[7 * NN + pop[i]] = i + 1;
}

// ---------------- fp64 in-place Gauss-Jordan inverse, all in SMEM ----------------
// Emits MT = (inv(proj)+I)^T directly split into slots 18-20.
__global__ __launch_bounds__(1024)
void inv_kernel(const float* __restrict__ proj) {
    extern __shared__ double S[];            // 128*128
    __shared__ double pv[128];
    __shared__ int    pi[128];
    __shared__ int    perm[128];

    int a = blockIdx.x;
    int tid = threadIdx.x;
    int c = tid & 127, r0 = (tid >> 7) << 4;

    for (int idx = tid; idx < 16384; idx += 1024)
        S[idx] = (double)proj[(size_t)a * 16384 + idx];
    __syncthreads();

    for (int k = 0; k < 128; k++) {
        if (tid < 128) {
            pv[tid] = (tid >= k) ? fabs(S[tid * 128 + k]) : -1.0;
            pi[tid] = tid;
        }
        __syncthreads();
        for (int s = 64; s > 0; s >>= 1) {
            if (tid < s && pv[tid + s] > pv[tid]) { pv[tid] = pv[tid + s]; pi[tid] = pi[tid + s]; }
            __syncthreads();
        }
        int piv = pi[0];
        if (tid == 0) perm[k] = piv;
        if (tid < 128) {
            double vk = S[k * 128 + tid];
            if (piv != k) {
                double vp = S[piv * 128 + tid];
                S[piv * 128 + tid] = vk;
                vk = vp;
            }
            pv[tid] = vk;
        }
        __syncthreads();
        double d = pv[k];
        if (tid < 128) {
            double nv = ((tid == k) ? 1.0 : pv[tid]) / d;
            S[k * 128 + tid] = nv;
            pv[tid] = nv;
        }
        __syncthreads();
        double rk = pv[c];
        double f[16];
        #pragma unroll
        for (int m = 0; m < 16; m++) {
            int r = r0 + m;
            f[m] = (r == k) ? 0.0 : S[r * 128 + k];
        }
        __syncthreads();
        #pragma unroll
        for (int m = 0; m < 16; m++) {
            int r = r0 + m;
            if (r != k) {
                double v = S[r * 128 + c];
                if (c == k) v = 0.0;
                S[r * 128 + c] = v - f[m] * rk;
            }
        }
        __syncthreads();
    }
    for (int k = 127; k >= 0; k--) {
        int p = perm[k];
        if (p != k && tid < 128) {
            double t = S[tid * 128 + k];
            S[tid * 128 + k] = S[tid * 128 + p];
            S[tid * 128 + p] = t;
        }
        __syncthreads();
    }
    uint32_t* dh = g_ws + (size_t)(18 + a) * 16384;
    for (int idx = tid; idx < 8192; idx += 1024) {
        int o = idx >> 6, w = idx & 63;
        int i0 = 2 * w, i1 = 2 * w + 1;
        float v0 = (float)(S[i0 * 128 + o] + (i0 == o ? 1.0 : 0.0));
        float v1 = (float)(S[i1 * 128 + o] + (i1 == o ? 1.0 : 0.0));
        uint32_t lo;
        uint32_t hi = packsplit(v0, v1, lo);
        dh[o * 128 + w]      = hi;
        dh[o * 128 + 64 + w] = lo;
    }
}

// ---------------- CSR build -------------------------------------------------------
__device__ __forceinline__ void graph_ptrs(int g, const int* eia, const int* eif,
                                           const int** gi, const int** si) {
    if (g < 3)      { *gi = eia + (size_t)g * 2 * EE;            *si = eia + (size_t)g * 2 * EE + EE; }
    else if (g < 6) { *gi = eia + (size_t)(g - 3) * 2 * EE + EE; *si = eia + (size_t)(g - 3) * 2 * EE; }
    else            { *gi = eif + EFN;                           *si = eif; }
}

__global__ void hist_k(const int* __restrict__ eia, const int* __restrict__ eif) {
    int g = blockIdx.y;
    const int *gi, *si;
    graph_ptrs(g, eia, eif, &gi, &si);
    int e = blockIdx.x * blockDim.x + threadIdx.x;
    if (e < EE) atomicAdd(g_fillip + (size_t)g * NN + si[e], 1);
}

__global__ __launch_bounds__(1024)
void scan_p1() {
    int g = blockIdx.y, b = blockIdx.x, tid = threadIdx.x;
    int i = b * 1024 + tid;
    int v = (i < NN) ? g_fillip[(size_t)g * NN + i] : 0;
    #pragma unroll
    for (int o = 16; o; o >>= 1) v += __shfl_down_sync(~0u, v, o);
    __shared__ int w[32];
    if ((tid & 31) == 0) w[tid >> 5] = v;
    __syncthreads();
    if (tid < 32) {
        int x = w[tid];
        #pragma unroll
        for (int o = 16; o; o >>= 1) x += __shfl_down_sync(~0u, x, o);
        if (tid == 0) g_bsum[g * NBLK + b] = x;
    }
}
// merged p2+p3: each block reduces preceding block sums, then block-local scan
__global__ __launch_bounds__(1024)
void scan_p23() {
    int g = blockIdx.y, b = blockIdx.x, tid = threadIdx.x;
    __shared__ int sb[128];
    __shared__ int s[1024];
    if (tid < 128) sb[tid] = (tid < b) ? g_bsum[g * NBLK + tid] : 0;
    __syncthreads();
    for (int off = 64; off; off >>= 1) {
        if (tid < off) sb[tid] += sb[tid + off];
        __syncthreads();
    }
    int base = sb[0];
    int i = b * 1024 + tid;
    int v = (i < NN) ? g_fillip[(size_t)g * NN + i] : 0;
    s[tid] = v;
    __syncthreads();
    for (int off = 1; off < 1024; off <<= 1) {
        int t = (tid >= off) ? s[tid - off] : 0;
        __syncthreads();
        s[tid] += t;
        __syncthreads();
    }
    if (i < NN) {
        int val = base + s[tid] - v;
        g_rowptr[(size_t)g * (NN + 1) + i] = val;
        g_fillip[(size_t)g * NN + i] = val;
    }
    if (b == NBLK - 1 && tid == 1023)
        g_rowptr[(size_t)g * (NN + 1) + NN] = base + s[1023];
}

__global__ void fill_k(const int* __restrict__ eia, const int* __restrict__ eif) {
    int g = blockIdx.y;
    const int *gi, *si;
    graph_ptrs(g, eia, eif, &gi, &si);
    int e = blockIdx.x * blockDim.x + threadIdx.x;
    if (e < EE) {
        int pos = atomicAdd(g_fillip + (size_t)g * NN + si[e], 1);
        g_eord[(size_t)g * EE + pos] = gi[e];
    }
}

// ---------------- gather-mean: always writes split ------------------------------
// SRCSPLIT=false: src f32 rows (128 floats); true: src split rows (128 words).
template<bool SRCSPLIT>
__global__ __launch_bounds__(256)
void gather_mean(const void* __restrict__ data, long dataBStr,   // elements per a
                 int gbase, int fam4, uint32_t* __restrict__ outp, long outBStr) {
    int a = blockIdx.y;
    int g = (fam4 && a == 3) ? 6 : (gbase + a);
    const char* dbase = (const char*)data + (size_t)a * dataBStr * 4;
    uint32_t* o = outp + (size_t)a * outBStr;
    const int* rp = g_rowptr + (size_t)g * (NN + 1);
    const int* eo = g_eord + (size_t)g * EE;

    int node = blockIdx.x * 8 + (threadIdx.x >> 5);
    int lane = threadIdx.x & 31;
    if (node >= NN) return;
    int s = rp[node], e = rp[node + 1];
    float inv = 1.0f / fmaxf((float)(e - s), 1.0f);

    if (SRCSPLIT) {
        const uint32_t* d = (const uint32_t*)dbase;
        float acc[8];
        #pragma unroll
        for (int q = 0; q < 8; q++) acc[q] = 0.0f;
        int j = s;
        for (; j + 1 < e; j += 2) {
            uint4 u0 = *(const uint4*)(d + (size_t)eo[j] * ROWW + lane * 4);
            uint4 u1 = *(const uint4*)(d + (size_t)eo[j + 1] * ROWW + lane * 4);
            float2 f;
            f = bf2f(u0.x); acc[0] += f.x; acc[1] += f.y;
            f = bf2f(u0.y); acc[2] += f.x; acc[3] += f.y;
            f = bf2f(u0.z); acc[4] += f.x; acc[5] += f.y;
            f = bf2f(u0.w); acc[6] += f.x; acc[7] += f.y;
            f = bf2f(u1.x); acc[0] += f.x; acc[1] += f.y;
            f = bf2f(u1.y); acc[2] += f.x; acc[3] += f.y;
            f = bf2f(u1.z); acc[4] += f.x; acc[5] += f.y;
            f = bf2f(u1.w); acc[6] += f.x; acc[7] += f.y;
        }
        if (j < e) {
            uint4 u = *(const uint4*)(d + (size_t)eo[j] * ROWW + lane * 4);
            float2 f;
            f = bf2f(u.x); acc[0] += f.x; acc[1] += f.y;
            f = bf2f(u.y); acc[2] += f.x; acc[3] += f.y;
            f = bf2f(u.z); acc[4] += f.x; acc[5] += f.y;
            f = bf2f(u.w); acc[6] += f.x; acc[7] += f.y;
        }
        // lanes 0-15 hold hi-plane partials, 16-31 lo-plane partials of same cols
        #pragma unroll
        for (int q = 0; q < 8; q++)
            acc[q] += __shfl_down_sync(~0u, acc[q], 16);
        if (lane < 16) {
            uint4 h, l;
            float s0 = acc[0] * inv, s1 = acc[1] * inv, s2 = acc[2] * inv, s3 = acc[3] * inv;
            float s4 = acc[4] * inv, s5 = acc[5] * inv, s6 = acc[6] * inv, s7 = acc[7] * inv;
            h.x = packsplit(s0, s1, l.x);
            h.y = packsplit(s2, s3, l.y);
            h.z = packsplit(s4, s5, l.z);
            h.w = packsplit(s6, s7, l.w);
            *(uint4*)(o + (size_t)node * ROWW + lane * 4)      = h;
            *(uint4*)(o + (size_t)node * ROWW + 64 + lane * 4) = l;
        }
    } else {
        const float* d = (const float*)dbase;
        float4 acc = make_float4(0.f, 0.f, 0.f, 0.f);
        int j = s;
        for (; j + 3 < e; j += 4) {
            int g0 = eo[j], g1 = eo[j + 1], g2 = eo[j + 2], g3 = eo[j + 3];
            float4 v0 = ((const float4*)(d + (size_t)g0 * DD))[lane];
            float4 v1 = ((const float4*)(d + (size_t)g1 * DD))[lane];
            float4 v2 = ((const float4*)(d + (size_t)g2 * DD))[lane];
            float4 v3 = ((const float4*)(d + (size_t)g3 * DD))[lane];
            acc.x += (v0.x + v1.x) + (v2.x + v3.x);
            acc.y += (v0.y + v1.y) + (v2.y + v3.y);
            acc.z += (v0.z + v1.z) + (v2.z + v3.z);
            acc.w += (v0.w + v1.w) + (v2.w + v3.w);
        }
        if (j + 1 < e) {
            int g0 = eo[j], g1 = eo[j + 1];
            float4 v0 = ((const float4*)(d + (size_t)g0 * DD))[lane];
            float4 v1 = ((const float4*)(d + (size_t)g1 * DD))[lane];
            acc.x += v0.x + v1.x; acc.y += v0.y + v1.y;
            acc.z += v0.z + v1.z; acc.w += v0.w + v1.w;
            j += 2;
        }
        if (j < e) {
            float4 v = ((const float4*)(d + (size_t)eo[j] * DD))[lane];
            acc.x += v.x; acc.y += v.y; acc.z += v.z; acc.w += v.w;
        }
        acc.x *= inv; acc.y *= inv; acc.z *= inv; acc.w *= inv;
        // lane covers cols 4L..4L+3 -> words 2L, 2L+1
        uint2 h, l;
        h.x = packsplit(acc.x, acc.y, l.x);
        h.y = packsplit(acc.z, acc.w, l.y);
        *(uint2*)(o + (size_t)node * ROWW + lane * 2)      = h;
        *(uint2*)(o + (size_t)node * ROWW + 64 + lane * 2) = l;
    }
}

// ---------------- bf16 m16n8k16 fused GEMM, double-buffered -----------------------
// Out[row] = act( In1[row] @ W1^T + In2row @ W2^T + bias )
// A operands f32 or pre-split (A1S/A2S); W always pre-split; output f32 or split
// (OUTS). GIN/GOUT row indirection via ridx; SEL2 per-row In2 select (f32 only).
#define RSTR 20
static constexpr int STAGE_WORDS = 128 * RSTR;
static constexpr int GEMM_SMEM = 2048 + 2 * 4 * STAGE_WORDS * 4;   // 83968

template<bool HAS2, bool GIN, bool GOUT, bool RELU, bool HASBIAS, bool SEL2,
         bool A1S, bool A2S, bool OUTS>
__global__ __launch_bounds__(512)
void gemm_tc(const void* __restrict__ In1v, int in1Stride, long in1BStr,
             const uint32_t* __restrict__ W1s, long w1BStr,
             const void* __restrict__ In2v, int in2Stride, long in2BStr,
             const float* __restrict__ In2b, long in2bBStr, const int* __restrict__ sel2,
             const uint32_t* __restrict__ W2s, long w2BStr,
             const float* __restrict__ bias, long biasBStr,
             const int*   __restrict__ ridx,
             void* __restrict__ Outv, long outBStr,
             int nrows) {
    extern __shared__ __align__(16) char smem[];
    int*      sRow  = (int*)smem;                                  // 512 B
    float*    sBias = (float*)(smem + 512);                        // 512 B
    unsigned long long* sP2 = (unsigned long long*)(smem + 1024);  // 1024 B
    uint32_t* sBase = (uint32_t*)(smem + 2048);

    const char* In1 = (const char*)In1v + (size_t)blockIdx.y * (size_t)in1BStr * 4;
    const char* In2 = nullptr;
    if (HAS2) In2 = (const char*)In2v + (size_t)blockIdx.y * (size_t)in2BStr * 4;
    W1s += (size_t)blockIdx.y * w1BStr;
    if (HAS2) W2s += (size_t)blockIdx.y * w2BStr;
    if (SEL2) In2b += (size_t)blockIdx.y * in2bBStr;
    if (HASBIAS) bias += (size_t)blockIdx.y * biasBStr;
    char* Out = (char*)Outv + (size_t)blockIdx.y * (size_t)outBStr * 4;

    int tid = threadIdx.x, wid = tid >> 5, lane = tid & 31;
    int g = lane >> 2, tg = lane & 3;
    int warpM = wid >> 2, warpN = wid & 3;
    int row0 = blockIdx.x * 128;

    if (tid < 128) {
        int gr = row0 + tid;
        int e = 0;
        if (gr < nrows) e = GIN ? ridx[gr] : gr;
        sRow[tid] = e;
        if (HASBIAS) sBias[tid] = bias[tid];
        if (HAS2) {
            int g2 = (gr < nrows) ? gr : (nrows - 1);
            const char* pp;
            if (A2S) {
                pp = In2 + (size_t)g2 * 512;
            } else if (SEL2) {
                int s2 = sel2[g2];
                pp = (s2 > 0) ? (const char*)(In2b + (size_t)(s2 - 1) * DD)
                              : In2 + (size_t)g2 * (size_t)in2Stride * 4;
            } else {
                pp = In2 + (size_t)g2 * (size_t)in2Stride * 4;
            }
            sP2[tid] = (unsigned long long)pp;
        }
    }
    __syncthreads();

    float acc[2][4][4];
    #pragma unroll
    for (int mt = 0; mt < 2; mt++)
        #pragma unroll
        for (int nt = 0; nt < 4; nt++)
            #pragma unroll
            for (int i = 0; i < 4; i++) acc[mt][nt][i] = 0.0f;

    const int np = HAS2 ? 8 : 4;
    int frr = tid >> 2, fsg = (tid & 3) * 2;

    uint4 rAx0, rAx1, rBh, rBl;

    auto ldg = [&](int p) {
        int op = HAS2 ? (p >> 2) : 0;
        int kc = (p & 3) * 32;
        bool aspl = (op == 0) ? A1S : A2S;
        const char* ap;
        if (op == 0) {
            if (A1S) ap = In1 + (size_t)sRow[frr] * 512;
            else     ap = In1 + (size_t)sRow[frr] * (size_t)in1Stride * 4;
        } else {
            ap = (const char*)sP2[frr];
        }
        if (aspl) {
            const uint32_t* apw = (const uint32_t*)ap + (p & 3) * 16 + fsg * 2;
            rAx0 = *(const uint4*)apw;
            rAx1 = *(const uint4*)(apw + 64);
        } else {
            const float* apf = (const float*)ap + kc + fsg * 4;
            rAx0 = *(const uint4*)apf;
            rAx1 = *(const uint4*)(apf + 4);
        }
        const uint32_t* wsp = (op == 0) ? W1s : W2s;
        int wb = frr * 128 + (p & 3) * 16 + fsg * 2;
        rBh = *(const uint4*)(wsp + wb);
        rBl = *(const uint4*)(wsp + wb + 64);
    };
    auto sts = [&](int p) {
        int op = HAS2 ? (p >> 2) : 0;
        bool aspl = (op == 0) ? A1S : A2S;
        uint32_t* st  = sBase + (p & 1) * (4 * STAGE_WORDS);
        uint32_t* tAh = st;
        uint32_t* tAl = st + STAGE_WORDS;
        uint32_t* tBh = st + 2 * STAGE_WORDS;
        uint32_t* tBl = st + 3 * STAGE_WORDS;
        int wa = frr * RSTR + fsg * 2;
        if (aspl) {
            *(uint4*)&tAh[wa] = rAx0;
            *(uint4*)&tAl[wa] = rAx1;
        } else {
            float4 v0 = *(float4*)&rAx0;
            float4 v1 = *(float4*)&rAx1;
            uint4 h, l;
            h.x = packsplit(v0.x, v0.y, l.x);
            h.y = packsplit(v0.z, v0.w, l.y);
            h.z = packsplit(v1.x, v1.y, l.z);
            h.w = packsplit(v1.z, v1.w, l.w);
            *(uint4*)&tAh[wa] = h;
            *(uint4*)&tAl[wa] = l;
        }
        *(uint4*)&tBh[wa] = rBh;
        *(uint4*)&tBl[wa] = rBl;
    };

    ldg(0);
    sts(0);
    if (np > 1) ldg(1);
    __syncthreads();

    for (int p = 0; p < np; p++) {
        if (p + 1 < np) sts(p + 1);
        if (p + 2 < np) ldg(p + 2);
        uint32_t* st  = sBase + (p & 1) * (4 * STAGE_WORDS);
        uint32_t* sAhi = st;
        uint32_t* sAlo = st + STAGE_WORDS;
        uint32_t* sBhi = st + 2 * STAGE_WORDS;
        uint32_t* sBlo = st + 3 * STAGE_WORDS;
        #pragma unroll
        for (int ks = 0; ks < 2; ks++) {
            int wb = ks * 8 + tg;
            uint32_t aH[2][4], aL[2][4];
            #pragma unroll
            for (int mt = 0; mt < 2; mt++) {
                int rb = (warpM * 32 + mt * 16 + g) * RSTR;
                aH[mt][0] = sAhi[rb + wb];
                aH[mt][1] = sAhi[rb + 8 * RSTR + wb];
                aH[mt][2] = sAhi[rb + wb + 4];
                aH[mt][3] = sAhi[rb + 8 * RSTR + wb + 4];
                aL[mt][0] = sAlo[rb + wb];
                aL[mt][1] = sAlo[rb + 8 * RSTR + wb];
                aL[mt][2] = sAlo[rb + wb + 4];
                aL[mt][3] = sAlo[rb + 8 * RSTR + wb + 4];
            }
            #pragma unroll
            for (int nt = 0; nt < 4; nt++) {
                int nb = (warpN * 32 + nt * 8 + g) * RSTR;
                uint32_t bh0 = sBhi[nb + wb], bh1 = sBhi[nb + wb + 4];
                uint32_t bl0 = sBlo[nb + wb], bl1 = sBlo[nb + wb + 4];
                #pragma unroll
                for (int mt = 0; mt < 2; mt++) {
                    mma16(acc[mt][nt], aH[mt], bh0, bh1);
                    mma16(acc[mt][nt], aL[mt], bh0, bh1);
                    mma16(acc[mt][nt], aH[mt], bl0, bl1);
                }
            }
        }
        __syncthreads();
    }

    #pragma unroll
    for (int mt = 0; mt < 2; mt++) {
        #pragma unroll
        for (int half = 0; half < 2; half++) {
            int lr = warpM * 32 + mt * 16 + g + half * 8;
            int grow = row0 + lr;
            if (grow < nrows) {
                int orow = GOUT ? sRow[lr] : grow;
                #pragma unroll
                for (int nt = 0; nt < 4; nt++) {
                    int col = warpN * 32 + nt * 8 + tg * 2;
                    float v0 = acc[mt][nt][half * 2 + 0];
                    float v1 = acc[mt][nt][half * 2 + 1];
                    if (HASBIAS) { v0 += sBias[col]; v1 += sBias[col + 1]; }
                    if (RELU) { v0 = fmaxf(v0, 0.0f); v1 = fmaxf(v1, 0.0f); }
                    if (OUTS) {
                        uint32_t* ob = (uint32_t*)Out + (size_t)orow * ROWW;
                        uint32_t lo;
                        uint32_t hi = packsplit(v0, v1, lo);
                        int w = col >> 1;
                        ob[w]      = hi;
                        ob[w + 64] = lo;
                    } else {
                        float* ob = (float*)Out + (size_t)orow * 128;
                        float2 pp; pp.x = v0; pp.y = v1;
                        *(float2*)(ob + col) = pp;
                    }
                }
            }
        }
    }
}

// ---------------- host orchestration ----------------------------------------------
extern "C" void kernel_launch(void* const* d_in, const int* in_sizes, int n_in,
                              void* d_out, int out_size) {
    int iXI, iXA, iPF, iPOP, iEIA, iEIF, iPROJ, iAGGW, iAGGB,
        iWL1, iBL1, iWR1, iWL2, iBL2, iWR2, iWL3, iBL3, iWR3;
    if (in_sizes[3] == PP) {  // setup_inputs dict order
        iXI = 0; iXA = 1; iPF = 2; iPOP = 3; iEIA = 4; iEIF = 5;
        iPROJ = 6; iAGGW = 7; iAGGB = 8; iWL1 = 9; iBL1 = 10; iWR1 = 11;
        iWL2 = 12; iBL2 = 13; iWR2 = 14; iWL3 = 15; iBL3 = 16; iWR3 = 17;
    } else {                  // reference() signature order
        iXI = 0; iXA = 1; iPF = 2; iPROJ = 3; iAGGW = 4; iAGGB = 5;
        iWL1 = 6; iBL1 = 7; iWR1 = 8; iWL2 = 9; iBL2 = 10; iWR2 = 11;
        iWL3 = 12; iBL3 = 13; iWR3 = 14; iPOP = 15; iEIA = 16; iEIF = 17;
    }

    const float* xi   = (const float*)d_in[iXI];
    const float* xa   = (const float*)d_in[iXA];
    const float* pf   = (const float*)d_in[iPF];
    const int*   pop  = (const int*)d_in[iPOP];
    const int*   eia  = (const int*)d_in[iEIA];
    const int*   eif  = (const int*)d_in[iEIF];
    const float* proj = (const float*)d_in[iPROJ];
    const float* aggW = (const float*)d_in[iAGGW];
    const float* aggB = (const float*)d_in[iAGGB];
    const float* wl1  = (const float*)d_in[iWL1];
    const float* bl1  = (const float*)d_in[iBL1];
    const float* wr1  = (const float*)d_in[iWR1];
    const float* wl2  = (const float*)d_in[iWL2];
    const float* bl2  = (const float*)d_in[iBL2];
    const float* wr2  = (const float*)d_in[iWR2];
    const float* wl3  = (const float*)d_in[iWL3];
    const float* bl3  = (const float*)d_in[iBL3];
    const float* wr3  = (const float*)d_in[iWR3];

    float* out = (float*)d_out;  // [x_ind_out (N*D)] then [x_att_out (A*N*D)]

    float *hbuf;
    uint32_t *ws, *xbs, *aggs;
    int *fillip;
    cudaGetSymbolAddress((void**)&hbuf,   g_hbuf);
    cudaGetSymbolAddress((void**)&ws,     g_ws);
    cudaGetSymbolAddress((void**)&xbs,    g_xbs);
    cudaGetSymbolAddress((void**)&aggs,   g_aggs);
    cudaGetSymbolAddress((void**)&fillip, g_fillip);
    const int* ipop = fillip + 7 * NN;
    uint32_t* agg3s = aggs + (size_t)3 * NN * ROWW;
    const long AGGB_STR = (long)NN * ROWW;

    cudaFuncSetAttribute(inv_kernel, cudaFuncAttributeMaxDynamicSharedMemorySize, 131072);
    cudaFuncSetAttribute(gemm_tc<false, false, false, false, false, false, false, false, true>,
                         cudaFuncAttributeMaxDynamicSharedMemorySize, GEMM_SMEM);
    cudaFuncSetAttribute(gemm_tc<true, true, false, true, true, false, false, false, false>,
                         cudaFuncAttributeMaxDynamicSharedMemorySize, GEMM_SMEM);
    cudaFuncSetAttribute(gemm_tc<true, false, false, false, true, true, true, false, true>,
                         cudaFuncAttributeMaxDynamicSharedMemorySize, GEMM_SMEM);
    cudaFuncSetAttribute(gemm_tc<false, true, true, true, false, false, true, false, true>,
                         cudaFuncAttributeMaxDynamicSharedMemorySize, GEMM_SMEM);
    cudaFuncSetAttribute(gemm_tc<true, false, false, false, true, false, true, true, false>,
                         cudaFuncAttributeMaxDynamicSharedMemorySize, GEMM_SMEM);
    cudaFuncSetAttribute(gemm_tc<true, false, false, false, true, false, true, false, false>,
                         cudaFuncAttributeMaxDynamicSharedMemorySize, GEMM_SMEM);

    const int gP = (PP + 127) / 128;  // 391
    const int gN = (NN + 127) / 128;  // 782
    const int eB = (EE + 255) / 256;
    const int nB = (NN + 7) / 8;

    // --- CSR build first: node order puts first gather at stream node 5 (ncu -s 5) ---
    cudaMemsetAsync(fillip, 0, (size_t)8 * NN * sizeof(int), 0);       // node 0
    hist_k<<<dim3(eB, 7), 256>>>(eia, eif);                            // node 1
    scan_p1<<<dim3(NBLK, 7), 1024>>>();                                // node 2
    scan_p23<<<dim3(NBLK, 7), 1024>>>();                               // node 3
    fill_k<<<dim3(eB, 7), 256>>>(eia, eif);                            // node 4

    // 5+10) agg slots 0-2 (graphs 0-2) and 3 (family): seg-mean of xi  // node 5
    gather_mean<false><<<dim3(nB, 4), 256>>>(xi, 0, 0, 1, aggs, AGGB_STR);

    // --- prep: weight pre-split, inverse (emits MT), ipop ---
    wconv<<<18, 1024>>>(aggW, wl1, wr1, wl2, wr2, wl3, wr3, proj);
    inv_kernel<<<AA, 1024, 131072>>>(proj);
    ipop_k<<<(PP + 255) / 256, 256>>>(pop);

    // fold: C[a] = aggW2 @ proj[a]^T  -> split slots 21-23
    gemm_tc<false, false, false, false, false, false, false, false, true>
        <<<dim3(1, AA), 512, GEMM_SMEM>>>(
        aggW + 128, 256, 0,
        ws + (size_t)15 * 16384, 16384,
        nullptr, 0, 0, nullptr, 0, nullptr,
        nullptr, 0,
        nullptr, 0, nullptr,
        ws + (size_t)21 * 16384, 16384,
        128);

    // 4) hbuf[a][i] = relu(xa[a][pop[i]] @ aggW1^T + pf[i,a,:] @ C[a]^T + aggB)
    gemm_tc<true, true, false, true, true, false, false, false, false>
        <<<dim3(gP, AA), 512, GEMM_SMEM>>>(
        xa, DD, (long)ND,
        ws, 0,
        pf, AA * DD, (long)DD, nullptr, 0, nullptr,
        ws + (size_t)21 * 16384, 16384,
        aggB, 0, pop,
        hbuf, (long)PD,
        PP);

    // 6) x_att_b = agg @ W_l1^T + b_l1 + x_att_a @ W_r1^T  (split in/out; xa/hbuf select)
    gemm_tc<true, false, false, false, true, true, true, false, true>
        <<<dim3(gN, AA), 512, GEMM_SMEM>>>(
        aggs, 0, AGGB_STR,
        ws + (size_t)1 * 16384, 16384,
        xa, DD, (long)ND, hbuf, (long)PD, ipop,
        ws + (size_t)4 * 16384, 16384,
        bl1, DD, nullptr,
        xbs, AGGB_STR,
        NN);

    // 7) population rows: x_att_b[pop] = relu(x_att_b[pop] @ (inv(proj)+I))
    gemm_tc<false, true, true, true, false, false, true, false, true>
        <<<dim3(gP, AA), 512, GEMM_SMEM>>>(
        xbs, 0, AGGB_STR,
        ws + (size_t)18 * 16384, 16384,
        nullptr, 0, 0, nullptr, 0, nullptr,
        nullptr, 0,
        nullptr, 0, pop,
        xbs, AGGB_STR,
        PP);

    // 8) agg slots 0-2 = seg-mean of x_att_b over src (graphs 3-5, split source)
    gather_mean<true><<<dim3(nB, AA), 256>>>(xbs, AGGB_STR, 3, 0, aggs, AGGB_STR);

    // 9) x_att_out = agg @ W_l2^T + b_l2 + x_att_b @ W_r2^T  -> d_out[N*D:]
    gemm_tc<true, false, false, false, true, false, true, true, false>
        <<<dim3(gN, AA), 512, GEMM_SMEM>>>(
        aggs, 0, AGGB_STR,
        ws + (size_t)7 * 16384, 16384,
        xbs, 0, AGGB_STR, nullptr, 0, nullptr,
        ws + (size_t)10 * 16384, 16384,
        bl2, DD, nullptr,
        out + ND, (long)ND,
        NN);

    // 11) x_ind_out = agg3 @ W_l3^T + b_l3 + xi @ W_r3^T -> d_out[0:]
    gemm_tc<true, false, false, false, true, false, true, false, false>
        <<<dim3(gN, 1), 512, GEMM_SMEM>>>(
        agg3s, 0, 0,
        ws + (size_t)13 * 16384, 0,
        xi, DD, 0, nullptr, 0, nullptr,
        ws + (size_t)14 * 16384, 0,
        bl3, 0, nullptr,
        out, 0,
        NN);
}

// round 17
// speedup vs baseline: 1.1322x; 1.1322x over previous
#include <cuda_runtime.h>
#include <cuda_bf16.h>
#include <cstdint>
#include <cstddef>

#define NN 100000
#define DD 128
#define AA 3
#define PP 50000
#define EE 500000
#define EFN 500000

#define ND  ((size_t)NN * DD)
#define PD  ((size_t)PP * DD)
#define NBLK 98   // (NN + 1023) / 1024

// ---------------- scratch (static device globals; no allocation) ----------------
__device__ float    g_hbuf  [AA * PP * DD];   // compact h rows (population)
__device__ float    g_xatt_b[AA * NN * DD];
__device__ float    g_agg   [4 * NN * DD];    // slots 0-2: attr agg; slot 3: family agg
__device__ float    g_fdummy[AA * 128 * 128]; // fold GEMM f32 out (unused)
__device__ int      g_ipop  [NN];             // node -> pop position+1 (0 = absent)
// pre-split weights: slot s = 16384 words; hi at [s*16384 + n*64 + w], lo at +8192.
// slots: 0 aggW1, 1-3 wl1, 4-6 wr1, 7-9 wl2, 10-12 wr2, 13 wl3, 14 wr3,
//        15-17 proj, 18-20 MT (inv), 21-23 C (fold)
__device__ __align__(16) uint32_t g_ws[24 * 16384];
// CSR structures for the 7 edge graphs (0-2: attr dst-seg, 3-5: attr src-seg, 6: family)
__device__ int    g_rowptr[7 * (NN + 1)];
__device__ int    g_fill  [7 * NN];
__device__ int    g_eord  [7 * EE];
__device__ int    g_bsum  [7 * NBLK];

// m16n8k16 bf16 mma (sm_80+ portable)
__device__ __forceinline__ void mma16(float* c, const uint32_t* a, uint32_t b0, uint32_t b1) {
    asm volatile("mma.sync.aligned.m16n8k16.row.col.f32.bf16.bf16.f32 "
                 "{%0,%1,%2,%3}, {%4,%5,%6,%7}, {%8,%9}, {%0,%1,%2,%3};"
                 : "+f"(c[0]), "+f"(c[1]), "+f"(c[2]), "+f"(c[3])
                 : "r"(a[0]), "r"(a[1]), "r"(a[2]), "r"(a[3]), "r"(b0), "r"(b1));
}
// split (x,y) into packed bf16x2 hi + lo
__device__ __forceinline__ uint32_t packsplit(float x, float y, uint32_t& lopack) {
    float hx = __bfloat162float(__float2bfloat16(x));
    float hy = __bfloat162float(__float2bfloat16(y));
    uint32_t hi;
    asm("cvt.rn.bf16x2.f32 %0, %1, %2;" : "=r"(hi) : "f"(hy), "f"(hx));
    asm("cvt.rn.bf16x2.f32 %0, %1, %2;" : "=r"(lopack) : "f"(y - hy), "f"(x - hx));
    return hi;
}

// ---------------- weight pre-split: f32 [n][k] -> bf16 hi/lo slot ---------------
__global__ __launch_bounds__(1024)
void wconv(const float* __restrict__ aggW, const float* __restrict__ wl1,
           const float* __restrict__ wr1, const float* __restrict__ wl2,
           const float* __restrict__ wr2, const float* __restrict__ wl3,
           const float* __restrict__ wr3, const float* __restrict__ proj) {
    int b = blockIdx.x;
    const float* src; int st;
    if (b == 0)       { src = aggW;                   st = 256; }
    else if (b < 4)   { src = wl1 + (b - 1) * 16384;  st = 128; }
    else if (b < 7)   { src = wr1 + (b - 4) * 16384;  st = 128; }
    else if (b < 10)  { src = wl2 + (b - 7) * 16384;  st = 128; }
    else if (b < 13)  { src = wr2 + (b - 10) * 16384; st = 128; }
    else if (b == 13) { src = wl3;                    st = 128; }
    else if (b == 14) { src = wr3;                    st = 128; }
    else              { src = proj + (b - 15) * 16384; st = 128; }
    uint32_t* dh = g_ws + (size_t)b * 16384;
    for (int idx = threadIdx.x; idx < 8192; idx += 1024) {
        int n = idx >> 6, w = idx & 63;
        float x = src[(size_t)n * st + 2 * w];
        float y = src[(size_t)n * st + 2 * w + 1];
        uint32_t lo;
        uint32_t hi = packsplit(x, y, lo);
        dh[n * 64 + w] = hi;
        dh[8192 + n * 64 + w] = lo;
    }
}

// ---------------- ipop: node -> population position + 1 -------------------------
__global__ void ipop_k(const int* __restrict__ pop) {
    int i = blockIdx.x * blockDim.x + threadIdx.x;
    if (i < PP) g_ipop[pop[i]] = i + 1;
}

// ---------------- fp64 in-place Gauss-Jordan inverse, all in SMEM ---------------
// Emits MT = (inv(proj)+I)^T directly in split format (slots 18-20).
__global__ __launch_bounds__(1024)
void inv_kernel(const float* __restrict__ proj) {
    extern __shared__ double S[];            // 128*128
    __shared__ double pv[128];
    __shared__ int    pi[128];
    __shared__ int    perm[128];

    int a = blockIdx.x;
    int tid = threadIdx.x;
    int c = tid & 127, r0 = (tid >> 7) << 4;

    for (int idx = tid; idx < 16384; idx += 1024)
        S[idx] = (double)proj[(size_t)a * 16384 + idx];
    __syncthreads();

    for (int k = 0; k < 128; k++) {
        if (tid < 128) {
            pv[tid] = (tid >= k) ? fabs(S[tid * 128 + k]) : -1.0;
            pi[tid] = tid;
        }
        __syncthreads();
        for (int s = 64; s > 0; s >>= 1) {
            if (tid < s && pv[tid + s] > pv[tid]) { pv[tid] = pv[tid + s]; pi[tid] = pi[tid + s]; }
            __syncthreads();
        }
        int piv = pi[0];
        if (tid == 0) perm[k] = piv;
        if (tid < 128) {
            double vk = S[k * 128 + tid];
            if (piv != k) {
                double vp = S[piv * 128 + tid];
                S[piv * 128 + tid] = vk;
                vk = vp;
            }
            pv[tid] = vk;
        }
        __syncthreads();
        double d = pv[k];
        if (tid < 128) {
            double nv = ((tid == k) ? 1.0 : pv[tid]) / d;
            S[k * 128 + tid] = nv;
            pv[tid] = nv;
        }
        __syncthreads();
        double rk = pv[c];
        double f[16];
        #pragma unroll
        for (int m = 0; m < 16; m++) {
            int r = r0 + m;
            f[m] = (r == k) ? 0.0 : S[r * 128 + k];
        }
        __syncthreads();
        #pragma unroll
        for (int m = 0; m < 16; m++) {
            int r = r0 + m;
            if (r != k) {
                double v = S[r * 128 + c];
                if (c == k) v = 0.0;
                S[r * 128 + c] = v - f[m] * rk;
            }
        }
        __syncthreads();
    }
    for (int k = 127; k >= 0; k--) {
        int p = perm[k];
        if (p != k && tid < 128) {
            double t = S[tid * 128 + k];
            S[tid * 128 + k] = S[tid * 128 + p];
            S[tid * 128 + p] = t;
        }
        __syncthreads();
    }
    // MT[o][i] = inv[i][o] + (i==o), pre-split to slot 18+a
    uint32_t* dh = g_ws + (size_t)(18 + a) * 16384;
    for (int idx = tid; idx < 8192; idx += 1024) {
        int o = idx >> 6, w = idx & 63;
        int i0 = 2 * w, i1 = 2 * w + 1;
        float v0 = (float)(S[i0 * 128 + o] + (i0 == o ? 1.0 : 0.0));
        float v1 = (float)(S[i1 * 128 + o] + (i1 == o ? 1.0 : 0.0));
        uint32_t lo;
        uint32_t hi = packsplit(v0, v1, lo);
        dh[o * 64 + w] = hi;
        dh[8192 + o * 64 + w] = lo;
    }
}

// ---------------- CSR build ------------------------------------------------------
__device__ __forceinline__ void graph_ptrs(int g, const int* eia, const int* eif,
                                           const int** gi, const int** si) {
    if (g < 3)      { *gi = eia + (size_t)g * 2 * EE;            *si = eia + (size_t)g * 2 * EE + EE; }
    else if (g < 6) { *gi = eia + (size_t)(g - 3) * 2 * EE + EE; *si = eia + (size_t)(g - 3) * 2 * EE; }
    else            { *gi = eif + EFN;                           *si = eif; }
}

__global__ void hist_k(const int* __restrict__ eia, const int* __restrict__ eif) {
    int g = blockIdx.y;
    const int *gi, *si;
    graph_ptrs(g, eia, eif, &gi, &si);
    int e = blockIdx.x * blockDim.x + threadIdx.x;
    if (e < EE) atomicAdd(g_fill + (size_t)g * NN + si[e], 1);
}

__global__ __launch_bounds__(1024)
void scan_p1() {
    int g = blockIdx.y, b = blockIdx.x, tid = threadIdx.x;
    int i = b * 1024 + tid;
    int v = (i < NN) ? g_fill[(size_t)g * NN + i] : 0;
    #pragma unroll
    for (int o = 16; o; o >>= 1) v += __shfl_down_sync(~0u, v, o);
    __shared__ int w[32];
    if ((tid & 31) == 0) w[tid >> 5] = v;
    __syncthreads();
    if (tid < 32) {
        int x = w[tid];
        #pragma unroll
        for (int o = 16; o; o >>= 1) x += __shfl_down_sync(~0u, x, o);
        if (tid == 0) g_bsum[g * NBLK + b] = x;
    }
}
__global__ void scan_p2() {
    int wid = threadIdx.x >> 5, lane = threadIdx.x & 31;
    if (wid < 7 && lane == 0) {
        int run = 0;
        for (int j = 0; j < NBLK; j++) {
            int t = g_bsum[wid * NBLK + j];
            g_bsum[wid * NBLK + j] = run;
            run += t;
        }
        g_rowptr[(size_t)wid * (NN + 1) + NN] = run;
    }
}
__global__ __launch_bounds__(1024)
void scan_p3() {
    int g = blockIdx.y, b = blockIdx.x, tid = threadIdx.x;
    int i = b * 1024 + tid;
    int v = (i < NN) ? g_fill[(size_t)g * NN + i] : 0;
    __shared__ int s[1024];
    s[tid] = v;
    __syncthreads();
    for (int off = 1; off < 1024; off <<= 1) {
        int t = (tid >= off) ? s[tid - off] : 0;
        __syncthreads();
        s[tid] += t;
        __syncthreads();
    }
    if (i < NN) {
        int val = g_bsum[g * NBLK + b] + s[tid] - v;
        g_rowptr[(size_t)g * (NN + 1) + i] = val;
        g_fill[(size_t)g * NN + i] = val;
    }
}

__global__ void fill_k(const int* __restrict__ eia, const int* __restrict__ eif) {
    int g = blockIdx.y;
    const int *gi, *si;
    graph_ptrs(g, eia, eif, &gi, &si);
    int e = blockIdx.x * blockDim.x + threadIdx.x;
    if (e < EE) {
        int pos = atomicAdd(g_fill + (size_t)g * NN + si[e], 1);
        g_eord[(size_t)g * EE + pos] = gi[e];
    }
}

// ---------------- gather-mean (x4 unroll for MLP) --------------------------------
__global__ __launch_bounds__(256)
void gather_mean(const float* __restrict__ data, long dataBStr,
                 int gbase, int fam4, float* __restrict__ outp, long outBStr) {
    int a = blockIdx.y;
    int g = (fam4 && a == 3) ? 6 : (gbase + a);
    const float* d = data + (size_t)a * dataBStr;
    float* o = outp + (size_t)a * outBStr;
    const int* rp = g_rowptr + (size_t)g * (NN + 1);
    const int* eo = g_eord + (size_t)g * EE;

    int node = blockIdx.x * 8 + (threadIdx.x >> 5);
    int lane = threadIdx.x & 31;
    if (node >= NN) return;
    int s = rp[node], e = rp[node + 1];
    float4 acc = make_float4(0.f, 0.f, 0.f, 0.f);
    int j = s;
    for (; j + 3 < e; j += 4) {
        int g0 = eo[j], g1 = eo[j + 1], g2 = eo[j + 2], g3 = eo[j + 3];
        float4 v0 = ((const float4*)(d + (size_t)g0 * DD))[lane];
        float4 v1 = ((const float4*)(d + (size_t)g1 * DD))[lane];
        float4 v2 = ((const float4*)(d + (size_t)g2 * DD))[lane];
        float4 v3 = ((const float4*)(d + (size_t)g3 * DD))[lane];
        acc.x += (v0.x + v1.x) + (v2.x + v3.x);
        acc.y += (v0.y + v1.y) + (v2.y + v3.y);
        acc.z += (v0.z + v1.z) + (v2.z + v3.z);
        acc.w += (v0.w + v1.w) + (v2.w + v3.w);
    }
    if (j + 1 < e) {
        int g0 = eo[j], g1 = eo[j + 1];
        float4 v0 = ((const float4*)(d + (size_t)g0 * DD))[lane];
        float4 v1 = ((const float4*)(d + (size_t)g1 * DD))[lane];
        acc.x += v0.x + v1.x; acc.y += v0.y + v1.y;
        acc.z += v0.z + v1.z; acc.w += v0.w + v1.w;
        j += 2;
    }
    if (j < e) {
        float4 v = ((const float4*)(d + (size_t)eo[j] * DD))[lane];
        acc.x += v.x; acc.y += v.y; acc.z += v.z; acc.w += v.w;
    }
    float inv = 1.0f / fmaxf((float)(e - s), 1.0f);
    acc.x *= inv; acc.y *= inv; acc.z *= inv; acc.w *= inv;
    ((float4*)(o + (size_t)node * DD))[lane] = acc;
}

// ---------------- bf16 m16n8k16 fused GEMM, double-buffered ----------------------
// Out[row] = act( In1[row] @ W1^T + In2row @ W2^T + bias )
// W operands pre-split (hi at [n*64+w], lo at +8192). GIN/GOUT row indirection via
// ridx; SEL2 selects In2 row from In2b[sel2-1] or In2; WSOUT additionally emits the
// output pre-split into a weight slot (for the fold).
#define RSTR 20
static constexpr int STAGE_WORDS = 128 * RSTR;
static constexpr int GEMM_SMEM = 2048 + 2 * 4 * STAGE_WORDS * 4;   // 83968

template<bool HAS2, bool GIN, bool GOUT, bool RELU, bool HASBIAS, bool SEL2, bool WSOUT>
__global__ __launch_bounds__(512)
void gemm_tc(const float* __restrict__ In1, int in1Stride, long in1BStr,
             const uint32_t* __restrict__ W1s, long w1BStr,
             const float* __restrict__ In2, int in2Stride, long in2BStr,
             const float* __restrict__ In2b, long in2bBStr, const int* __restrict__ sel2,
             const uint32_t* __restrict__ W2s, long w2BStr,
             const float* __restrict__ bias, long biasBStr,
             const int*   __restrict__ ridx,
             float* __restrict__ Out, long outBStr,
             uint32_t* __restrict__ wsOut, long wsBStr,
             int nrows) {
    extern __shared__ __align__(16) char smem[];
    int*      sRow  = (int*)smem;                            // 512 B
    float*    sBias = (float*)(smem + 512);                  // 512 B
    unsigned long long* sP2 = (unsigned long long*)(smem + 1024);  // 1024 B
    uint32_t* sBase = (uint32_t*)(smem + 2048);

    {
        long a = blockIdx.y;
        In1 += a * in1BStr; W1s += a * w1BStr;
        if (HAS2) { In2 += a * in2BStr; W2s += a * w2BStr; }
        if (SEL2) In2b += a * in2bBStr;
        if (HASBIAS) bias += a * biasBStr;
        if (WSOUT) wsOut += a * wsBStr;
        Out += a * outBStr;
    }

    int tid = threadIdx.x, wid = tid >> 5, lane = tid & 31;
    int g = lane >> 2, tg = lane & 3;
    int warpM = wid >> 2, warpN = wid & 3;
    int row0 = blockIdx.x * 128;

    if (tid < 128) {
        int gr = row0 + tid;
        int e = 0;
        if (gr < nrows) e = GIN ? ridx[gr] : gr;
        sRow[tid] = e;
        if (HASBIAS) sBias[tid] = bias[tid];
        if (HAS2) {
            int g2 = (gr < nrows) ? gr : (nrows - 1);
            const float* p;
            if (SEL2) {
                int s2 = sel2[g2];
                p = (s2 > 0) ? In2b + (size_t)(s2 - 1) * DD
                             : In2 + (size_t)g2 * in2Stride;
            } else {
                p = In2 + (size_t)g2 * in2Stride;
            }
            sP2[tid] = (unsigned long long)p;
        }
    }
    __syncthreads();

    float acc[2][4][4];
    #pragma unroll
    for (int mt = 0; mt < 2; mt++)
        #pragma unroll
        for (int nt = 0; nt < 4; nt++)
            #pragma unroll
            for (int i = 0; i < 4; i++) acc[mt][nt][i] = 0.0f;

    const int np = HAS2 ? 8 : 4;
    int frr = tid >> 2, fsg = (tid & 3) * 2;

    float4 rA[2];
    uint4 rBh, rBl;

    auto ldg = [&](int p) {
        int op = HAS2 ? (p >> 2) : 0;
        int kc = (p & 3) * 32;
        const float* ap;
        if (op == 0) ap = In1 + (size_t)sRow[frr] * in1Stride;
        else         ap = (const float*)sP2[frr];
        rA[0] = *(const float4*)(ap + kc + fsg * 4);
        rA[1] = *(const float4*)(ap + kc + fsg * 4 + 4);
        const uint32_t* ws = (op == 0) ? W1s : W2s;
        int wbase = frr * 64 + (p & 3) * 16 + fsg * 2;
        rBh = *(const uint4*)(ws + wbase);
        rBl = *(const uint4*)(ws + 8192 + wbase);
    };
    auto sts = [&](int p) {
        uint32_t* st  = sBase + (p & 1) * (4 * STAGE_WORDS);
        uint32_t* tAh = st;
        uint32_t* tAl = st + STAGE_WORDS;
        uint32_t* tBh = st + 2 * STAGE_WORDS;
        uint32_t* tBl = st + 3 * STAGE_WORDS;
        #pragma unroll
        for (int q = 0; q < 2; q++) {
            int seg = fsg + q;
            int wa = frr * RSTR + seg * 2;
            uint32_t lo0, lo1;
            uint32_t hi0 = packsplit(rA[q].x, rA[q].y, lo0);
            uint32_t hi1 = packsplit(rA[q].z, rA[q].w, lo1);
            tAh[wa] = hi0; tAh[wa + 1] = hi1;
            tAl[wa] = lo0; tAl[wa + 1] = lo1;
        }
        *(uint4*)&tBh[frr * RSTR + fsg * 2] = rBh;
        *(uint4*)&tBl[frr * RSTR + fsg * 2] = rBl;
    };

    ldg(0);
    sts(0);
    if (np > 1) ldg(1);
    __syncthreads();

    for (int p = 0; p < np; p++) {
        if (p + 1 < np) sts(p + 1);
        if (p + 2 < np) ldg(p + 2);
        uint32_t* st  = sBase + (p & 1) * (4 * STAGE_WORDS);
        uint32_t* sAhi = st;
        uint32_t* sAlo = st + STAGE_WORDS;
        uint32_t* sBhi = st + 2 * STAGE_WORDS;
        uint32_t* sBlo = st + 3 * STAGE_WORDS;
        #pragma unroll
        for (int ks = 0; ks < 2; ks++) {
            int wb = ks * 8 + tg;
            uint32_t aH[2][4], aL[2][4];
            #pragma unroll
            for (int mt = 0; mt < 2; mt++) {
                int rb = (warpM * 32 + mt * 16 + g) * RSTR;
                aH[mt][0] = sAhi[rb + wb];
                aH[mt][1] = sAhi[rb + 8 * RSTR + wb];
                aH[mt][2] = sAhi[rb + wb + 4];
                aH[mt][3] = sAhi[rb + 8 * RSTR + wb + 4];
                aL[mt][0] = sAlo[rb + wb];
                aL[mt][1] = sAlo[rb + 8 * RSTR + wb];
                aL[mt][2] = sAlo[rb + wb + 4];
                aL[mt][3] = sAlo[rb + 8 * RSTR + wb + 4];
            }
            #pragma unroll
            for (int nt = 0; nt < 4; nt++) {
                int nb = (warpN * 32 + nt * 8 + g) * RSTR;
                uint32_t bh0 = sBhi[nb + wb], bh1 = sBhi[nb + wb + 4];
                uint32_t bl0 = sBlo[nb + wb], bl1 = sBlo[nb + wb + 4];
                #pragma unroll
                for (int mt = 0; mt < 2; mt++) {
                    mma16(acc[mt][nt], aH[mt], bh0, bh1);
                    mma16(acc[mt][nt], aL[mt], bh0, bh1);
                    mma16(acc[mt][nt], aH[mt], bl0, bl1);
                }
            }
        }
        __syncthreads();
    }

    #pragma unroll
    for (int mt = 0; mt < 2; mt++) {
        #pragma unroll
        for (int half = 0; half < 2; half++) {
            int lr = warpM * 32 + mt * 16 + g + half * 8;
            int grow = row0 + lr;
            if (grow < nrows) {
                int orow = GOUT ? sRow[lr] : grow;
                float* ob = Out + (size_t)orow * 128;
                #pragma unroll
                for (int nt = 0; nt < 4; nt++) {
                    int col = warpN * 32 + nt * 8 + tg * 2;
                    float v0 = acc[mt][nt][half * 2 + 0];
                    float v1 = acc[mt][nt][half * 2 + 1];
                    if (HASBIAS) { v0 += sBias[col]; v1 += sBias[col + 1]; }
                    if (RELU) { v0 = fmaxf(v0, 0.0f); v1 = fmaxf(v1, 0.0f); }
                    float2 pp; pp.x = v0; pp.y = v1;
                    *(float2*)(ob + col) = pp;
                    if (WSOUT) {
                        uint32_t lo;
                        uint32_t hi = packsplit(v0, v1, lo);
                        wsOut[(size_t)orow * 64 + (col >> 1)] = hi;
                        wsOut[8192 + (size_t)orow * 64 + (col >> 1)] = lo;
                    }
                }
            }
        }
    }
}

// ---------------- host orchestration -------------------------------------------
extern "C" void kernel_launch(void* const* d_in, const int* in_sizes, int n_in,
                              void* d_out, int out_size) {
    int iXI, iXA, iPF, iPOP, iEIA, iEIF, iPROJ, iAGGW, iAGGB,
        iWL1, iBL1, iWR1, iWL2, iBL2, iWR2, iWL3, iBL3, iWR3;
    if (in_sizes[3] == PP) {  // setup_inputs dict order
        iXI = 0; iXA = 1; iPF = 2; iPOP = 3; iEIA = 4; iEIF = 5;
        iPROJ = 6; iAGGW = 7; iAGGB = 8; iWL1 = 9; iBL1 = 10; iWR1 = 11;
        iWL2 = 12; iBL2 = 13; iWR2 = 14; iWL3 = 15; iBL3 = 16; iWR3 = 17;
    } else {                  // reference() signature order
        iXI = 0; iXA = 1; iPF = 2; iPROJ = 3; iAGGW = 4; iAGGB = 5;
        iWL1 = 6; iBL1 = 7; iWR1 = 8; iWL2 = 9; iBL2 = 10; iWR2 = 11;
        iWL3 = 12; iBL3 = 13; iWR3 = 14; iPOP = 15; iEIA = 16; iEIF = 17;
    }

    const float* xi   = (const float*)d_in[iXI];
    const float* xa   = (const float*)d_in[iXA];
    const float* pf   = (const float*)d_in[iPF];
    const int*   pop  = (const int*)d_in[iPOP];
    const int*   eia  = (const int*)d_in[iEIA];
    const int*   eif  = (const int*)d_in[iEIF];
    const float* proj = (const float*)d_in[iPROJ];
    const float* aggW = (const float*)d_in[iAGGW];
    const float* aggB = (const float*)d_in[iAGGB];
    const float* wl1  = (const float*)d_in[iWL1];
    const float* bl1  = (const float*)d_in[iBL1];
    const float* wr1  = (const float*)d_in[iWR1];
    const float* wl2  = (const float*)d_in[iWL2];
    const float* bl2  = (const float*)d_in[iBL2];
    const float* wr2  = (const float*)d_in[iWR2];
    const float* wl3  = (const float*)d_in[iWL3];
    const float* bl3  = (const float*)d_in[iBL3];
    const float* wr3  = (const float*)d_in[iWR3];

    float* out = (float*)d_out;  // [x_ind_out (N*D)] then [x_att_out (A*N*D)]

    float *hbuf, *xatt_b, *agg, *fdummy;
    uint32_t* ws;
    int *fillp, *ipop;
    cudaGetSymbolAddress((void**)&hbuf,   g_hbuf);
    cudaGetSymbolAddress((void**)&xatt_b, g_xatt_b);
    cudaGetSymbolAddress((void**)&agg,    g_agg);
    cudaGetSymbolAddress((void**)&fdummy, g_fdummy);
    cudaGetSymbolAddress((void**)&ws,     g_ws);
    cudaGetSymbolAddress((void**)&fillp,  g_fill);
    cudaGetSymbolAddress((void**)&ipop,   g_ipop);
    float* agg3 = agg + 3 * ND;

    cudaFuncSetAttribute(inv_kernel, cudaFuncAttributeMaxDynamicSharedMemorySize, 131072);
    cudaFuncSetAttribute(gemm_tc<false, false, false, false, false, false, true>,
                         cudaFuncAttributeMaxDynamicSharedMemorySize, GEMM_SMEM);
    cudaFuncSetAttribute(gemm_tc<true, true, false, true, true, false, false>,
                         cudaFuncAttributeMaxDynamicSharedMemorySize, GEMM_SMEM);
    cudaFuncSetAttribute(gemm_tc<true, false, false, false, true, true, false>,
                         cudaFuncAttributeMaxDynamicSharedMemorySize, GEMM_SMEM);
    cudaFuncSetAttribute(gemm_tc<false, true, true, true, false, false, false>,
                         cudaFuncAttributeMaxDynamicSharedMemorySize, GEMM_SMEM);
    cudaFuncSetAttribute(gemm_tc<true, false, false, false, true, false, false>,
                         cudaFuncAttributeMaxDynamicSharedMemorySize, GEMM_SMEM);

    const int gP = (PP + 127) / 128;  // 391
    const int gN = (NN + 127) / 128;  // 782
    const int eB = (EE + 255) / 256;
    const int nB = (NN + 7) / 8;

    // ---- fork a side stream for the CSR-independent branch -----------------
    // (created per call and intentionally leaked: destroying a forked stream
    //  before the harness ends its capture is illegal; handles are host-side)
    cudaStream_t s1;
    cudaStreamCreateWithFlags(&s1, cudaStreamNonBlocking);
    cudaEvent_t evF, evJ;
    cudaEventCreateWithFlags(&evF, cudaEventDisableTiming);
    cudaEventCreateWithFlags(&evJ, cudaEventDisableTiming);
    cudaEventRecord(evF, 0);
    cudaStreamWaitEvent(s1, evF, 0);

    // ---- branch B (stream s1): weights, inverse, ipop, fold, step 4 --------
    wconv<<<18, 1024, 0, s1>>>(aggW, wl1, wr1, wl2, wr2, wl3, wr3, proj);
    inv_kernel<<<AA, 1024, 131072, s1>>>(proj);
    cudaMemsetAsync(ipop, 0, (size_t)NN * sizeof(int), s1);
    ipop_k<<<(PP + 255) / 256, 256, 0, s1>>>(pop);

    // fold: C[a] = aggW2 @ proj[a]^T -> split slots 21-23
    gemm_tc<false, false, false, false, false, false, true><<<dim3(1, AA), 512, GEMM_SMEM, s1>>>(
        aggW + 128, 256, 0,
        ws + (size_t)15 * 16384, 16384,
        nullptr, 0, 0, nullptr, 0, nullptr,
        nullptr, 0,
        nullptr, 0, nullptr,
        fdummy, 16384,
        ws + (size_t)21 * 16384, 16384,
        128);

    // 4) hbuf[a][i] = relu(xa[a][pop[i]] @ aggW1^T + pf[i,a,:] @ C[a]^T + aggB)
    gemm_tc<true, true, false, true, true, false, false><<<dim3(gP, AA), 512, GEMM_SMEM, s1>>>(
        xa, DD, (long)ND,
        ws, 0,
        pf, AA * DD, (long)DD, nullptr, 0, nullptr,
        ws + (size_t)21 * 16384, 16384,
        aggB, 0, pop,
        hbuf, (long)PD,
        nullptr, 0,
        PP);

    // ---- branch A (stream 0): CSR build + first gathers ---------------------
    cudaMemsetAsync(fillp, 0, (size_t)7 * NN * sizeof(int), 0);
    hist_k<<<dim3(eB, 7), 256>>>(eia, eif);
    scan_p1<<<dim3(NBLK, 7), 1024>>>();
    scan_p2<<<1, 256>>>();
    scan_p3<<<dim3(NBLK, 7), 1024>>>();
    fill_k<<<dim3(eB, 7), 256>>>(eia, eif);

    // 5+10) agg = seg-mean of xi: graphs 0-2 (dst-seg) and 6 (family)
    gather_mean<<<dim3(nB, 4), 256>>>(xi, 0, 0, 1, agg, (long)ND);

    // ---- join ---------------------------------------------------------------
    cudaEventRecord(evJ, s1);
    cudaStreamWaitEvent(0, evJ, 0);

    // 6) x_att_b = agg @ W_l1^T + b_l1 + x_att_a @ W_r1^T  (x_att_a via hbuf/xa select)
    gemm_tc<true, false, false, false, true, true, false><<<dim3(gN, AA), 512, GEMM_SMEM>>>(
        agg, DD, (long)ND,
        ws + (size_t)1 * 16384, 16384,
        xa, DD, (long)ND, hbuf, (long)PD, ipop,
        ws + (size_t)4 * 16384, 16384,
        bl1, DD, nullptr,
        xatt_b, (long)ND,
        nullptr, 0,
        NN);

    // 7) population rows: x_att_b[pop] = relu(x_att_b[pop] @ (inv(proj)+I))
    gemm_tc<false, true, true, true, false, false, false><<<dim3(gP, AA), 512, GEMM_SMEM>>>(
        xatt_b, DD, (long)ND,
        ws + (size_t)18 * 16384, 16384,
        nullptr, 0, 0, nullptr, 0, nullptr,
        nullptr, 0,
        nullptr, 0, pop,
        xatt_b, (long)ND,
        nullptr, 0,
        PP);

    // 8) agg = seg-mean of x_att_b over src (graphs 3-5)
    gather_mean<<<dim3(nB, AA), 256>>>(xatt_b, (long)ND, 3, 0, agg, (long)ND);

    // 9) x_att_out = agg @ W_l2^T + b_l2 + x_att_b @ W_r2^T  -> d_out[N*D:]
    gemm_tc<true, false, false, false, true, false, false><<<dim3(gN, AA), 512, GEMM_SMEM>>>(
        agg, DD, (long)ND,
        ws + (size_t)7 * 16384, 16384,
        xatt_b, DD, (long)ND, nullptr, 0, nullptr,
        ws + (size_t)10 * 16384, 16384,
        bl2, DD, nullptr,
        out + ND, (long)ND,
        nullptr, 0,
        NN);

    // 11) x_ind_out = agg3 @ W_l3^T + b_l3 + xi @ W_r3^T -> d_out[0:]
    gemm_tc<true, false, false, false, true, false, false><<<dim3(gN, 1), 512, GEMM_SMEM>>>(
        agg3, DD, 0,
        ws + (size_t)13 * 16384, 0,
        xi, DD, 0, nullptr, 0, nullptr,
        ws + (size_t)14 * 16384, 0,
        bl3, 0, nullptr,
        out, 0,
        nullptr, 0,
        NN);
}